// round 2
// baseline (speedup 1.0000x reference)
#include <cuda_runtime.h>
#include <cuda_fp16.h>
#include <cstdint>
#include <cstddef>

#define NWIN 4096
#define NH 4
#define LQ 49
#define HD 32
#define ED 128
#define QK_SCALE 0.17677669529663687f

// ---------------- device scratch (no dynamic allocation allowed) ----------------
__device__ __half d_WqkvT[NH * 3 * HD * ED];          // [(h*3+m)*32+d][k]  fp16, de-interleaved
__device__ __half d_WprojT[ED * ED];                  // [n][k] fp16 (transposed W_proj)
__device__ __half d_AO[(size_t)NWIN * LQ * ED];       // attention output, head-concat, fp16

// ---------------- prep: convert + reorder weights to fp16 ----------------
__global__ void prep_kernel(const float* __restrict__ Wqkv,
                            const float* __restrict__ Wproj) {
    int idx = blockIdx.x * blockDim.x + threadIdx.x;
    const int total1 = NH * 3 * HD * ED;              // 49152
    if (idx < total1) {
        int k = idx & 127;
        int t = idx >> 7;
        int d = t & 31;
        t >>= 5;
        int m = t % 3;                                // 0=q 1=k 2=v
        int h = t / 3;
        // einops 'b l (d f k)': column = d*12 + h*3 + m
        d_WqkvT[idx] = __float2half(Wqkv[k * (3 * ED) + d * 12 + h * 3 + m]);
    } else {
        int j = idx - total1;
        if (j < ED * ED) {
            int k = j & 127, n = j >> 7;
            d_WprojT[j] = __float2half(Wproj[k * ED + n]);
        }
    }
}

// ---------------- mma helpers (m16n8k16 f16 -> f32) ----------------
__device__ __forceinline__ uint32_t ldh2(const __half* p) {
    return *reinterpret_cast<const uint32_t*>(p);
}
__device__ __forceinline__ void sth2(__half* p, float a, float b) {
    *reinterpret_cast<__half2*>(p) = __floats2half2_rn(a, b);
}
__device__ __forceinline__ void mma_f16(float* c,
                                        uint32_t a0, uint32_t a1, uint32_t a2, uint32_t a3,
                                        uint32_t b0, uint32_t b1) {
    asm volatile(
        "mma.sync.aligned.m16n8k16.row.col.f32.f16.f16.f32 "
        "{%0,%1,%2,%3},{%4,%5,%6,%7},{%8,%9},{%0,%1,%2,%3};\n"
        : "+f"(c[0]), "+f"(c[1]), "+f"(c[2]), "+f"(c[3])
        : "r"(a0), "r"(a1), "r"(a2), "r"(a3), "r"(b0), "r"(b1));
}

// ---------------- smem layout for attention kernel (bytes) ----------------
#define XS_OFF  0                                   // half [64][136]  x window (fp16, zero-padded rows)
#define WQ_OFF  (XS_OFF + 64*136*2)                 // half [3][32][136] per-head W slices [n][k]
#define QS_OFF  (WQ_OFF + 3*32*136*2)               // half [64][40]
#define KS_OFF  (QS_OFF + 64*40*2)                  // half [56][40]
#define VT_OFF  (KS_OFF + 56*40*2)                  // half [32][72]  V transposed, rows>=49 zero
#define PS_OFF  (VT_OFF + 32*72*2)                  // half [64][72]  softmax probs, cols>=49 zero
#define RTH_OFF (PS_OFF + 64*72*2)                  // float [13][32] rel_pos_h table
#define RTW_OFF (RTH_OFF + 13*32*4)                 // float [13][32] rel_pos_w table
#define RH_OFF  (RTW_OFF + 13*32*4)                 // float [64][8]  rel_h[i][kh]
#define RW_OFF  (RH_OFF + 64*8*4)                   // float [64][8]  rel_w[i][kw]
#define SS_OFF  (RW_OFF + 64*8*4)                   // float [64][60] logits
#define BQ_OFF  (SS_OFF + 64*60*4)                  // float [96] reordered qkv bias
#define SMEM1   (BQ_OFF + 96*4)                     // = 90112 bytes

// ---------------- fused qkv + attention kernel ----------------
__global__ __launch_bounds__(256, 2)
void attn_kernel(const float* __restrict__ x,
                 const float* __restrict__ bqkv,
                 const float* __restrict__ rph,
                 const float* __restrict__ rpw) {
    extern __shared__ char smem[];
    __half* xs  = (__half*)(smem + XS_OFF);
    __half* wqm = (__half*)(smem + WQ_OFF);
    __half* Qs  = (__half*)(smem + QS_OFF);
    __half* Ks  = (__half*)(smem + KS_OFF);
    __half* Vt  = (__half*)(smem + VT_OFF);
    __half* Ps  = (__half*)(smem + PS_OFF);
    float*  rth = (float*)(smem + RTH_OFF);
    float*  rtw = (float*)(smem + RTW_OFF);
    float*  rhs = (float*)(smem + RH_OFF);
    float*  rws = (float*)(smem + RW_OFF);
    float*  Ss  = (float*)(smem + SS_OFF);
    float*  bqs = (float*)(smem + BQ_OFF);

    const int tid  = threadIdx.x;
    const int lane = tid & 31;
    const int warp = tid >> 5;
    const int win  = blockIdx.x >> 2;
    const int h    = blockIdx.x & 3;

    // ---- load x window -> fp16 smem (pad rows 49..63 with zeros) ----
    {
        const float* gx = x + (size_t)win * (LQ * ED);
        for (int r = warp; r < 64; r += 8) {
            if (r < LQ) {
                float4 f = ((const float4*)(gx + r * ED))[lane];
                *(__half2*)&xs[r * 136 + lane * 4]     = __floats2half2_rn(f.x, f.y);
                *(__half2*)&xs[r * 136 + lane * 4 + 2] = __floats2half2_rn(f.z, f.w);
            } else {
                *(uint32_t*)&xs[r * 136 + lane * 4]     = 0u;
                *(uint32_t*)&xs[r * 136 + lane * 4 + 2] = 0u;
            }
        }
        // per-head W slices: 96 rows of 128 halfs
        const __half* gw = d_WqkvT + (size_t)h * 3 * HD * ED;
        for (int j = warp; j < 96; j += 8) {
            const __half* srow = gw + j * ED;
            __half* drow = wqm + (j >> 5) * (32 * 136) + (j & 31) * 136;
            *(uint2*)&drow[lane * 4] = *(const uint2*)&srow[lane * 4];
        }
        // rel tables (shared across heads): 13*32 floats each
        for (int i = tid; i < 416; i += 256) { rth[i] = rph[i]; rtw[i] = rpw[i]; }
        // reordered bias: bqs[m*32+d]
        for (int i = tid; i < 96; i += 256) {
            int m = i >> 5, d = i & 31;
            bqs[i] = bqkv[d * 12 + h * 3 + m];
        }
    }
    __syncthreads();

    const int mt  = warp & 3;   // M tile (16 rows each)
    const int nh2 = warp >> 2;  // N half
    const int g   = lane >> 2;
    const int tg  = lane & 3;

    // ---- QKV GEMM: [64,32]x3 = xs[64,128] @ W[128,32] ----
    {
        float accq[2][4], acck[2][4], accv[2][4];
        #pragma unroll
        for (int t = 0; t < 2; t++)
            #pragma unroll
            for (int i = 0; i < 4; i++) { accq[t][i] = 0.f; acck[t][i] = 0.f; accv[t][i] = 0.f; }

        #pragma unroll
        for (int ks = 0; ks < 8; ks++) {
            const int k0 = ks * 16 + tg * 2;
            const __half* ap = xs + (mt * 16 + g) * 136 + k0;
            uint32_t a0 = ldh2(ap);
            uint32_t a1 = ldh2(ap + 8 * 136);
            uint32_t a2 = ldh2(ap + 8);
            uint32_t a3 = ldh2(ap + 8 * 136 + 8);
            #pragma unroll
            for (int t = 0; t < 2; t++) {
                const int nrow = ((nh2 * 2 + t) * 8 + g) * 136 + k0;
                { const __half* bp = wqm + nrow;                 mma_f16(accq[t], a0,a1,a2,a3, ldh2(bp), ldh2(bp+8)); }
                { const __half* bp = wqm + 32*136 + nrow;        mma_f16(acck[t], a0,a1,a2,a3, ldh2(bp), ldh2(bp+8)); }
                { const __half* bp = wqm + 2*32*136 + nrow;      mma_f16(accv[t], a0,a1,a2,a3, ldh2(bp), ldh2(bp+8)); }
            }
        }
        const int r0 = mt * 16 + g;
        #pragma unroll
        for (int t = 0; t < 2; t++) {
            const int c0 = (nh2 * 2 + t) * 8 + tg * 2;
            float bq0 = bqs[c0], bq1 = bqs[c0 + 1];
            sth2(&Qs[r0 * 40 + c0],       accq[t][0] + bq0, accq[t][1] + bq1);
            sth2(&Qs[(r0 + 8) * 40 + c0], accq[t][2] + bq0, accq[t][3] + bq1);
            float bk0 = bqs[32 + c0], bk1 = bqs[32 + c0 + 1];
            if (r0 < 56)     sth2(&Ks[r0 * 40 + c0],       acck[t][0] + bk0, acck[t][1] + bk1);
            if (r0 + 8 < 56) sth2(&Ks[(r0 + 8) * 40 + c0], acck[t][2] + bk0, acck[t][3] + bk1);
            // V transposed; zero rows >= 49 so PV K-padding is clean
            float bv0 = bqs[64 + c0], bv1 = bqs[64 + c0 + 1];
            float v00 = (r0 < LQ)     ? (accv[t][0] + bv0) : 0.f;
            float v01 = (r0 < LQ)     ? (accv[t][1] + bv1) : 0.f;
            float v10 = (r0 + 8 < LQ) ? (accv[t][2] + bv0) : 0.f;
            float v11 = (r0 + 8 < LQ) ? (accv[t][3] + bv1) : 0.f;
            Vt[c0 * 72 + r0]           = __float2half(v00);
            Vt[(c0 + 1) * 72 + r0]     = __float2half(v01);
            Vt[c0 * 72 + r0 + 8]       = __float2half(v10);
            Vt[(c0 + 1) * 72 + r0 + 8] = __float2half(v11);
        }
    }
    __syncthreads();

    // ---- decomposed rel-pos bias: 49*7 dots of 32 for each of h/w ----
    for (int job = tid; job < 686; job += 256) {
        int which = (job >= 343);
        int t = which ? job - 343 : job;
        int i = t / 7, kk = t % 7;
        int qh = i / 7, qw = i % 7;
        const float* tab = which ? (rtw + (qw - kk + 6) * 32)
                                 : (rth + (qh - kk + 6) * 32);
        const __half* qrow = Qs + i * 40;
        float acc = 0.f;
        #pragma unroll
        for (int c = 0; c < 32; c++) acc += __half2float(qrow[c]) * tab[c];
        if (which) rws[i * 8 + kk] = acc;
        else       rhs[i * 8 + kk] = acc;
    }

    // ---- S = Q @ K^T * scale ----
    {
        float acc[4][4];
        #pragma unroll
        for (int t = 0; t < 4; t++)
            #pragma unroll
            for (int i = 0; i < 4; i++) acc[t][i] = 0.f;
        #pragma unroll
        for (int ks = 0; ks < 2; ks++) {
            const int k0 = ks * 16 + tg * 2;
            const __half* ap = Qs + (mt * 16 + g) * 40 + k0;
            uint32_t a0 = ldh2(ap), a1 = ldh2(ap + 8 * 40),
                     a2 = ldh2(ap + 8), a3 = ldh2(ap + 8 * 40 + 8);
            #pragma unroll
            for (int t = 0; t < 4; t++) {
                const int nt = nh2 * 4 + t;
                if (nt < 7) {
                    const __half* bp = Ks + (nt * 8 + g) * 40 + k0;
                    mma_f16(acc[t], a0, a1, a2, a3, ldh2(bp), ldh2(bp + 8));
                }
            }
        }
        const int r0 = mt * 16 + g;
        #pragma unroll
        for (int t = 0; t < 4; t++) {
            const int nt = nh2 * 4 + t;
            if (nt < 7) {
                const int j0 = nt * 8 + tg * 2;
                Ss[r0 * 60 + j0]           = acc[t][0] * QK_SCALE;
                Ss[r0 * 60 + j0 + 1]       = acc[t][1] * QK_SCALE;
                Ss[(r0 + 8) * 60 + j0]     = acc[t][2] * QK_SCALE;
                Ss[(r0 + 8) * 60 + j0 + 1] = acc[t][3] * QK_SCALE;
            }
        }
    }
    __syncthreads();

    // ---- softmax (fp32, stable) + bias; write P fp16 with zero K-padding ----
    if (tid < 64) {
        const int i = tid;
        __half* prow = Ps + i * 72;
        if (i < LQ) {
            float* srow = Ss + i * 60;
            float mx = -1e30f;
            #pragma unroll
            for (int kh = 0; kh < 7; kh++) {
                float bh = rhs[i * 8 + kh];
                #pragma unroll
                for (int kw = 0; kw < 7; kw++) {
                    float v = srow[kh * 7 + kw] + bh + rws[i * 8 + kw];
                    mx = fmaxf(mx, v);
                }
            }
            float sum = 0.f;
            #pragma unroll
            for (int kh = 0; kh < 7; kh++) {
                float bh = rhs[i * 8 + kh];
                #pragma unroll
                for (int kw = 0; kw < 7; kw++) {
                    float e = __expf(srow[kh * 7 + kw] + bh + rws[i * 8 + kw] - mx);
                    srow[kh * 7 + kw] = e;
                    sum += e;
                }
            }
            float inv = 1.f / sum;
            for (int j = 0; j < LQ; j++) prow[j] = __float2half(srow[j] * inv);
            for (int j = LQ; j < 64; j++) prow[j] = __float2half(0.f);
        } else {
            for (int j = 0; j < 64; j++) prow[j] = __float2half(0.f);
        }
    }
    __syncthreads();

    // ---- AO = P @ V  (write head-concat fp16 to global scratch) ----
    {
        float acc[2][4];
        #pragma unroll
        for (int t = 0; t < 2; t++)
            #pragma unroll
            for (int i = 0; i < 4; i++) acc[t][i] = 0.f;
        #pragma unroll
        for (int ks = 0; ks < 4; ks++) {
            const int k0 = ks * 16 + tg * 2;
            const __half* ap = Ps + (mt * 16 + g) * 72 + k0;
            uint32_t a0 = ldh2(ap), a1 = ldh2(ap + 8 * 72),
                     a2 = ldh2(ap + 8), a3 = ldh2(ap + 8 * 72 + 8);
            #pragma unroll
            for (int t = 0; t < 2; t++) {
                const int nt = nh2 * 2 + t;
                const __half* bp = Vt + (nt * 8 + g) * 72 + k0;
                mma_f16(acc[t], a0, a1, a2, a3, ldh2(bp), ldh2(bp + 8));
            }
        }
        const int r0 = mt * 16 + g;
        __half* gout = d_AO + (size_t)win * LQ * ED + h * HD;
        #pragma unroll
        for (int t = 0; t < 2; t++) {
            const int c0 = (nh2 * 2 + t) * 8 + tg * 2;
            if (r0 < LQ)
                *(__half2*)&gout[(size_t)r0 * ED + c0] = __floats2half2_rn(acc[t][0], acc[t][1]);
            if (r0 + 8 < LQ)
                *(__half2*)&gout[(size_t)(r0 + 8) * ED + c0] = __floats2half2_rn(acc[t][2], acc[t][3]);
        }
    }
}

// ---------------- proj GEMM: out = AO @ W_proj + b_proj (fp32 out) ----------------
#define SMEM2 (2 * 128 * 136 * 2 + 128 * 4)
__global__ __launch_bounds__(256, 2)
void proj_kernel(const float* __restrict__ bproj, float* __restrict__ out) {
    extern __shared__ char smem[];
    __half* As = (__half*)smem;                       // [128][136]
    __half* Bs = (__half*)(smem + 128 * 136 * 2);     // [128][136]
    float*  bs = (float*)(smem + 2 * 128 * 136 * 2);

    const int tid = threadIdx.x, lane = tid & 31, warp = tid >> 5;
    const __half* gA = d_AO + (size_t)blockIdx.x * 128 * ED;

    for (int i = tid; i < 128 * 16; i += 256) {
        int r = i >> 4, s = i & 15;
        *(uint4*)&As[r * 136 + s * 8] = *(const uint4*)&gA[r * 128 + s * 8];
        *(uint4*)&Bs[r * 136 + s * 8] = *(const uint4*)&d_WprojT[r * 128 + s * 8];
    }
    if (tid < 128) bs[tid] = bproj[tid];
    __syncthreads();

    const int g = lane >> 2, tg = lane & 3;
    float acc[16][4];
    #pragma unroll
    for (int nt = 0; nt < 16; nt++)
        #pragma unroll
        for (int i = 0; i < 4; i++) acc[nt][i] = 0.f;

    #pragma unroll
    for (int ks = 0; ks < 8; ks++) {
        const int k0 = ks * 16 + tg * 2;
        const __half* ap = As + (warp * 16 + g) * 136 + k0;
        uint32_t a0 = ldh2(ap), a1 = ldh2(ap + 8 * 136),
                 a2 = ldh2(ap + 8), a3 = ldh2(ap + 8 * 136 + 8);
        #pragma unroll
        for (int nt = 0; nt < 16; nt++) {
            const __half* bp = Bs + (nt * 8 + g) * 136 + k0;
            mma_f16(acc[nt], a0, a1, a2, a3, ldh2(bp), ldh2(bp + 8));
        }
    }
    const size_t r0 = (size_t)blockIdx.x * 128 + warp * 16 + g;
    #pragma unroll
    for (int nt = 0; nt < 16; nt++) {
        const int c0 = nt * 8 + tg * 2;
        float2 v0 = make_float2(acc[nt][0] + bs[c0], acc[nt][1] + bs[c0 + 1]);
        float2 v1 = make_float2(acc[nt][2] + bs[c0], acc[nt][3] + bs[c0 + 1]);
        *(float2*)&out[r0 * ED + c0]       = v0;
        *(float2*)&out[(r0 + 8) * ED + c0] = v1;
    }
}

// ---------------- launch ----------------
extern "C" void kernel_launch(void* const* d_in, const int* in_sizes, int n_in,
                              void* d_out, int out_size) {
    (void)in_sizes; (void)n_in; (void)out_size;
    const float* x    = (const float*)d_in[0];
    const float* Wqkv = (const float*)d_in[1];
    const float* bq   = (const float*)d_in[2];
    const float* Wp   = (const float*)d_in[3];
    const float* bp   = (const float*)d_in[4];
    const float* rph  = (const float*)d_in[5];
    const float* rpw  = (const float*)d_in[6];

    cudaFuncSetAttribute(attn_kernel, cudaFuncAttributeMaxDynamicSharedMemorySize, SMEM1);
    cudaFuncSetAttribute(proj_kernel, cudaFuncAttributeMaxDynamicSharedMemorySize, SMEM2);

    prep_kernel<<<256, 256>>>(Wqkv, Wp);
    attn_kernel<<<NWIN * NH, 256, SMEM1>>>(x, bq, rph, rpw);
    proj_kernel<<<(NWIN * LQ) / 128, 256, SMEM2>>>(bp, (float*)d_out);
}

// round 5
// speedup vs baseline: 1.1042x; 1.1042x over previous
#include <cuda_runtime.h>
#include <cuda_fp16.h>
#include <cstdint>
#include <cstddef>

#define NWIN 4096
#define NH 4
#define LQ 49
#define HD 32
#define ED 128
#define QK_SCALE 0.17677669529663687f

// ---------------- device weight scratch ----------------
__device__ __half d_WqkvT[NH * 3 * HD * ED];   // row n=(h*3+m)*32+d, col k  (fp16)
__device__ __half d_WprojT[ED * ED];           // [n][k] fp16

// ---------------- prep: convert + reorder weights ----------------
__global__ void prep_kernel(const float* __restrict__ Wqkv,
                            const float* __restrict__ Wproj) {
    int idx = blockIdx.x * blockDim.x + threadIdx.x;
    const int total1 = NH * 3 * HD * ED;              // 49152
    if (idx < total1) {
        int k = idx & 127;
        int t = idx >> 7;
        int d = t & 31;
        t >>= 5;
        int m = t % 3;
        int h = t / 3;
        d_WqkvT[idx] = __float2half(Wqkv[k * (3 * ED) + d * 12 + h * 3 + m]);
    } else {
        int j = idx - total1;
        if (j < ED * ED) {
            int k = j & 127, n = j >> 7;
            d_WprojT[j] = __float2half(Wproj[k * ED + n]);
        }
    }
}

// ---------------- helpers ----------------
__device__ __forceinline__ uint32_t pack2(float a, float b) {
    __half2 h = __floats2half2_rn(a, b);
    return *reinterpret_cast<uint32_t*>(&h);
}
__device__ __forceinline__ void sth2(__half* p, float a, float b) {
    *reinterpret_cast<__half2*>(p) = __floats2half2_rn(a, b);
}
__device__ __forceinline__ void mma_f16(float* c,
                                        uint32_t a0, uint32_t a1, uint32_t a2, uint32_t a3,
                                        uint32_t b0, uint32_t b1) {
    asm volatile(
        "mma.sync.aligned.m16n8k16.row.col.f32.f16.f16.f32 "
        "{%0,%1,%2,%3},{%4,%5,%6,%7},{%8,%9},{%0,%1,%2,%3};\n"
        : "+f"(c[0]), "+f"(c[1]), "+f"(c[2]), "+f"(c[3])
        : "r"(a0), "r"(a1), "r"(a2), "r"(a3), "r"(b0), "r"(b1));
}
__device__ __forceinline__ void ldsm4(uint32_t* r, const __half* p) {
    uint32_t a = (uint32_t)__cvta_generic_to_shared(p);
    asm volatile("ldmatrix.sync.aligned.m8n8.x4.shared.b16 {%0,%1,%2,%3},[%4];\n"
                 : "=r"(r[0]), "=r"(r[1]), "=r"(r[2]), "=r"(r[3]) : "r"(a));
}
// A-fragment (16x16 @ (r0,k0)): regs {a0,a1,a2,a3} = {(g,k0),(g+8,k0),(g,k0+8),(g+8,k0+8)}
__device__ __forceinline__ void ldA(uint32_t* r, const __half* base, int ld,
                                    int r0, int k0, int lane) {
    int m = lane >> 3;
    int row = r0 + (lane & 7) + ((m & 1) << 3);
    int col = k0 + ((m & 2) << 2);
    ldsm4(r, base + row * ld + col);
}
// B-fragments for 2 n-tiles (rows n0..n0+15 of B^T [n][k], k0..k0+15):
// regs = {nt0:k0, nt0:k0+8, nt1:k0, nt1:k0+8}
__device__ __forceinline__ void ldB(uint32_t* r, const __half* base, int ld,
                                    int n0, int k0, int lane) {
    int m = lane >> 3;
    int row = n0 + (lane & 7) + ((m & 2) << 2);
    int col = k0 + ((m & 1) << 3);
    ldsm4(r, base + row * ld + col);
}

// ---------------- smem layout (bytes) ----------------
#define XS_OFF  0                        // half [64][136] : x window, later AO (head-concat)
#define QS_OFF  17408                    // half [4][64][40]
#define KS_OFF  37888                    // half [4][64][40] (rows 56..63 scratch)
#define VT_OFF  58368                    // half [4][32][72] (cols>=49 zeroed)
#define RTH_OFF 76800                    // float [13][32]
#define RTW_OFF 78464                    // float [13][32]
#define RHS_OFF 80128                    // float [4][64][8]
#define RWS_OFF 88320                    // float [4][64][8]
#define BQS_OFF 96512                    // float [384] reordered qkv bias
#define BPS_OFF 98048                    // float [128] proj bias
#define SMEM1   98560

// ---------------- fully fused window-attention kernel ----------------
__global__ __launch_bounds__(512, 1)
void attn_kernel(const float* __restrict__ x,
                 const float* __restrict__ bqkv,
                 const float* __restrict__ rph,
                 const float* __restrict__ rpw,
                 const float* __restrict__ bproj,
                 float* __restrict__ out) {
    extern __shared__ char smem[];
    __half* xs  = (__half*)(smem + XS_OFF);
    __half* Qs  = (__half*)(smem + QS_OFF);
    __half* Ks  = (__half*)(smem + KS_OFF);
    __half* Vt  = (__half*)(smem + VT_OFF);
    float*  rth = (float*)(smem + RTH_OFF);
    float*  rtw = (float*)(smem + RTW_OFF);
    float*  rhs = (float*)(smem + RHS_OFF);
    float*  rws = (float*)(smem + RWS_OFF);
    float*  bqs = (float*)(smem + BQS_OFF);
    float*  bps = (float*)(smem + BPS_OFF);

    const int tid  = threadIdx.x;
    const int lane = tid & 31;
    const int warp = tid >> 5;          // 0..15
    const int win  = blockIdx.x;
    const int g    = lane >> 2;
    const int tg   = lane & 3;

    // ================= phase 1: loads / init =================
    {
        const float* gx = x + (size_t)win * (LQ * ED);
        for (int r = warp; r < 64; r += 16) {
            if (r < LQ) {
                float4 f = ((const float4*)(gx + r * ED))[lane];
                *(__half2*)&xs[r * 136 + lane * 4]     = __floats2half2_rn(f.x, f.y);
                *(__half2*)&xs[r * 136 + lane * 4 + 2] = __floats2half2_rn(f.z, f.w);
            } else {
                *(uint32_t*)&xs[r * 136 + lane * 4]     = 0u;
                *(uint32_t*)&xs[r * 136 + lane * 4 + 2] = 0u;
            }
        }
        for (int i = tid; i < 416; i += 512) { rth[i] = rph[i]; rtw[i] = rpw[i]; }
        for (int i = tid; i < 2048; i += 512) { rhs[i] = 0.f; rws[i] = 0.f; }
        for (int i = tid; i < 384; i += 512) {
            int hm = i >> 5, d = i & 31;          // hm = h*3+m
            int h = hm / 3, m = hm % 3;
            bqs[i] = bqkv[d * 12 + h * 3 + m];
        }
        if (tid < 128) bps[tid] = bproj[tid];
    }
    __syncthreads();

    // ================= phase 2: QKV GEMM [64x384] = xs[64x128] @ W^T =================
    // warp covers all 4 M-tiles x 3 n-tiles (nt = warp*3 + 0..2)
    {
        float acc[4][3][4];
        #pragma unroll
        for (int mt = 0; mt < 4; mt++)
            #pragma unroll
            for (int j = 0; j < 3; j++)
                #pragma unroll
                for (int i = 0; i < 4; i++) acc[mt][j][i] = 0.f;

        const int ntb = warp * 3;
        #pragma unroll
        for (int ks = 0; ks < 8; ks++) {
            const int k0 = ks * 16;
            uint32_t A[4][4];
            #pragma unroll
            for (int mt = 0; mt < 4; mt++) ldA(A[mt], xs, 136, mt * 16, k0, lane);
            #pragma unroll
            for (int j = 0; j < 3; j++) {
                const __half* bp = d_WqkvT + ((ntb + j) * 8 + g) * ED + k0 + 2 * tg;
                uint32_t b0 = *(const uint32_t*)bp;
                uint32_t b1 = *(const uint32_t*)(bp + 8);
                #pragma unroll
                for (int mt = 0; mt < 4; mt++)
                    mma_f16(acc[mt][j], A[mt][0], A[mt][1], A[mt][2], A[mt][3], b0, b1);
            }
        }
        // epilogue: route to Qs / Ks / Vt (warp-uniform branch on m)
        #pragma unroll
        for (int j = 0; j < 3; j++) {
            const int nt = ntb + j;
            const int h = nt / 12, m = (nt % 12) / 4, d0 = (nt % 4) * 8;
            const int d = d0 + 2 * tg;
            const float b0 = bqs[(h * 3 + m) * 32 + d];
            const float b1 = bqs[(h * 3 + m) * 32 + d + 1];
            #pragma unroll
            for (int mt = 0; mt < 4; mt++) {
                const int r0 = mt * 16 + g;
                float v00 = acc[mt][j][0] + b0, v01 = acc[mt][j][1] + b1;
                float v10 = acc[mt][j][2] + b0, v11 = acc[mt][j][3] + b1;
                if (m == 0) {
                    sth2(&Qs[(h * 64 + r0) * 40 + d],     v00, v01);
                    sth2(&Qs[(h * 64 + r0 + 8) * 40 + d], v10, v11);
                } else if (m == 1) {
                    sth2(&Ks[(h * 64 + r0) * 40 + d],     v00, v01);
                    sth2(&Ks[(h * 64 + r0 + 8) * 40 + d], v10, v11);
                } else {
                    if (r0 >= LQ)     { v00 = 0.f; v01 = 0.f; }
                    if (r0 + 8 >= LQ) { v10 = 0.f; v11 = 0.f; }
                    __half* vt = Vt + h * 32 * 72;
                    vt[d * 72 + r0]           = __float2half(v00);
                    vt[(d + 1) * 72 + r0]     = __float2half(v01);
                    vt[d * 72 + r0 + 8]       = __float2half(v10);
                    vt[(d + 1) * 72 + r0 + 8] = __float2half(v11);
                }
            }
        }
    }
    __syncthreads();

    // ================= phase 3: decomposed rel-pos bias =================
    // 4 heads x 343 x {h,w} = 2744 dot products of length 32 (half2 loads)
    for (int job = tid; job < 2744; job += 512) {
        int h = job / 686;
        int t = job % 686;
        int which = (t >= 343);
        if (which) t -= 343;
        int i = t / 7, kk = t % 7;
        int qh = i / 7, qw = i % 7;
        const float* tab = which ? (rtw + (qw - kk + 6) * 32)
                                 : (rth + (qh - kk + 6) * 32);
        const __half2* qrow = (const __half2*)(Qs + (h * 64 + i) * 40);
        float acc = 0.f;
        #pragma unroll
        for (int c = 0; c < 16; c++) {
            float2 qv = __half22float2(qrow[c]);
            acc += qv.x * tab[2 * c] + qv.y * tab[2 * c + 1];
        }
        if (which) rws[(h * 64 + i) * 8 + kk] = acc;
        else       rhs[(h * 64 + i) * 8 + kk] = acc;
    }
    __syncthreads();

    // ================= phase 4: S = QK^T, softmax (regs), AO = P@V =================
    // warp = h*4 + mt : handles 16 rows of one head
    {
        const int h = warp >> 2, mt = warp & 3;
        const __half* Qh = Qs + h * 64 * 40;
        const __half* Kh = Ks + h * 64 * 40;

        float sacc[7][4];
        #pragma unroll
        for (int nt = 0; nt < 7; nt++)
            #pragma unroll
            for (int i = 0; i < 4; i++) sacc[nt][i] = 0.f;

        #pragma unroll
        for (int ks = 0; ks < 2; ks++) {
            const int k0 = ks * 16;
            uint32_t A[4];
            ldA(A, Qh, 40, mt * 16, k0, lane);
            uint32_t Bb[4][4];
            #pragma unroll
            for (int p = 0; p < 4; p++) ldB(Bb[p], Kh, 40, p * 16, k0, lane);
            #pragma unroll
            for (int nt = 0; nt < 7; nt++) {
                const int p = nt >> 1, s = (nt & 1) * 2;
                mma_f16(sacc[nt], A[0], A[1], A[2], A[3], Bb[p][s], Bb[p][s + 1]);
            }
        }

        // softmax in registers; P[nt][0..1]=row g, P[nt][2..3]=row g+8
        float P[7][4];
        #pragma unroll
        for (int e = 0; e < 2; e++) {
            const int r = mt * 16 + g + 8 * e;
            const float* rh = rhs + (h * 64 + r) * 8;
            const float* rw = rws + (h * 64 + r) * 8;
            float v[7][2];
            float mx = -1e30f;
            #pragma unroll
            for (int nt = 0; nt < 7; nt++)
                #pragma unroll
                for (int cc = 0; cc < 2; cc++) {
                    const int jj = nt * 8 + 2 * tg + cc;
                    float val = -1e30f;
                    if (jj < LQ) val = sacc[nt][2 * e + cc] * QK_SCALE + rh[jj / 7] + rw[jj % 7];
                    v[nt][cc] = val;
                    mx = fmaxf(mx, val);
                }
            mx = fmaxf(mx, __shfl_xor_sync(0xffffffffu, mx, 1));
            mx = fmaxf(mx, __shfl_xor_sync(0xffffffffu, mx, 2));
            float sum = 0.f;
            #pragma unroll
            for (int nt = 0; nt < 7; nt++)
                #pragma unroll
                for (int cc = 0; cc < 2; cc++) {
                    float pe = __expf(v[nt][cc] - mx);
                    v[nt][cc] = pe;
                    sum += pe;
                }
            sum += __shfl_xor_sync(0xffffffffu, sum, 1);
            sum += __shfl_xor_sync(0xffffffffu, sum, 2);
            const float inv = 1.f / sum;
            #pragma unroll
            for (int nt = 0; nt < 7; nt++)
                #pragma unroll
                for (int cc = 0; cc < 2; cc++) P[nt][2 * e + cc] = v[nt][cc] * inv;
        }

        // repack P fragments as PV A-operands (no smem round-trip)
        uint32_t pa[4][4];
        #pragma unroll
        for (int kt = 0; kt < 4; kt++) {
            const int n0 = 2 * kt, n1 = 2 * kt + 1;
            pa[kt][0] = pack2(P[n0][0], P[n0][1]);
            pa[kt][1] = pack2(P[n0][2], P[n0][3]);
            if (n1 < 7) {
                pa[kt][2] = pack2(P[n1][0], P[n1][1]);
                pa[kt][3] = pack2(P[n1][2], P[n1][3]);
            } else { pa[kt][2] = 0u; pa[kt][3] = 0u; }
        }

        float oacc[4][4];
        #pragma unroll
        for (int nt = 0; nt < 4; nt++)
            #pragma unroll
            for (int i = 0; i < 4; i++) oacc[nt][i] = 0.f;

        const __half* Vh = Vt + h * 32 * 72;
        #pragma unroll
        for (int kt = 0; kt < 4; kt++) {
            uint32_t Bb[2][4];
            ldB(Bb[0], Vh, 72, 0,  kt * 16, lane);
            ldB(Bb[1], Vh, 72, 16, kt * 16, lane);
            #pragma unroll
            for (int nt = 0; nt < 4; nt++) {
                const int p = nt >> 1, s = (nt & 1) * 2;
                mma_f16(oacc[nt], pa[kt][0], pa[kt][1], pa[kt][2], pa[kt][3],
                        Bb[p][s], Bb[p][s + 1]);
            }
        }

        // write AO (head-concat, fp16) into xs region (x is dead)
        __half* AO = xs;
        #pragma unroll
        for (int nt = 0; nt < 4; nt++) {
            const int c = h * 32 + nt * 8 + 2 * tg;
            sth2(&AO[(mt * 16 + g) * 136 + c],     oacc[nt][0], oacc[nt][1]);
            sth2(&AO[(mt * 16 + g + 8) * 136 + c], oacc[nt][2], oacc[nt][3]);
        }
    }
    __syncthreads();

    // ================= phase 5: proj GEMM [64x128] = AO @ Wproj^T + b =================
    // warp covers all 4 M-tiles x 1 n-tile (nt = warp)
    {
        const __half* AO = xs;
        const int ntp = warp;
        float pacc[4][4];
        #pragma unroll
        for (int mt = 0; mt < 4; mt++)
            #pragma unroll
            for (int i = 0; i < 4; i++) pacc[mt][i] = 0.f;

        #pragma unroll
        for (int ks = 0; ks < 8; ks++) {
            const int k0 = ks * 16;
            uint32_t A[4][4];
            #pragma unroll
            for (int mt = 0; mt < 4; mt++) ldA(A[mt], AO, 136, mt * 16, k0, lane);
            const __half* bp = d_WprojT + (ntp * 8 + g) * ED + k0 + 2 * tg;
            uint32_t b0 = *(const uint32_t*)bp;
            uint32_t b1 = *(const uint32_t*)(bp + 8);
            #pragma unroll
            for (int mt = 0; mt < 4; mt++)
                mma_f16(pacc[mt], A[mt][0], A[mt][1], A[mt][2], A[mt][3], b0, b1);
        }

        const int c0 = ntp * 8 + 2 * tg;
        const float b0 = bps[c0], b1 = bps[c0 + 1];
        float* gout = out + (size_t)win * LQ * ED;
        #pragma unroll
        for (int mt = 0; mt < 4; mt++) {
            const int r0 = mt * 16 + g;
            if (r0 < LQ)
                *(float2*)&gout[(size_t)r0 * ED + c0] =
                    make_float2(pacc[mt][0] + b0, pacc[mt][1] + b1);
            if (r0 + 8 < LQ)
                *(float2*)&gout[(size_t)(r0 + 8) * ED + c0] =
                    make_float2(pacc[mt][2] + b0, pacc[mt][3] + b1);
        }
    }
}

// ---------------- launch ----------------
extern "C" void kernel_launch(void* const* d_in, const int* in_sizes, int n_in,
                              void* d_out, int out_size) {
    (void)in_sizes; (void)n_in; (void)out_size;
    const float* x    = (const float*)d_in[0];
    const float* Wqkv = (const float*)d_in[1];
    const float* bq   = (const float*)d_in[2];
    const float* Wp   = (const float*)d_in[3];
    const float* bp   = (const float*)d_in[4];
    const float* rph  = (const float*)d_in[5];
    const float* rpw  = (const float*)d_in[6];

    cudaFuncSetAttribute(attn_kernel, cudaFuncAttributeMaxDynamicSharedMemorySize, SMEM1);

    prep_kernel<<<256, 256>>>(Wqkv, Wp);
    attn_kernel<<<NWIN, 512, SMEM1>>>(x, bq, rph, rpw, bp, (float*)d_out);
}